// round 8
// baseline (speedup 1.0000x reference)
#include <cuda_runtime.h>

#define BB 256
#define TT 512
#define EMBD 64
#define HID 128

typedef unsigned long long u64t;

__device__ float g_pre1[(long)TT * BB * HID];   // [t][b][j]
__device__ float g_out1[(long)TT * BB * HID];   // [t][b][j]
__device__ float g_pre2[(long)TT * BB * HID];   // [t][b][j]
__device__ float g_h2[BB * HID];

__device__ __forceinline__ void ffma2(u64t& d, u64t a, u64t b) {
    asm("fma.rn.f32x2 %0, %1, %2, %0;" : "+l"(d) : "l"(a), "l"(b));
}
__device__ __forceinline__ float hsum2(u64t v) {
    unsigned lo, hi;
    asm("mov.b64 {%0,%1}, %2;" : "=r"(lo), "=r"(hi) : "l"(v));
    return __uint_as_float(lo) + __uint_as_float(hi);
}
__device__ __forceinline__ u64t pack2(float lo, float hi) {
    u64t r;
    asm("mov.b64 %0, {%1,%2};" : "=l"(r) : "r"(__float_as_uint(lo)), "r"(__float_as_uint(hi)));
    return r;
}

// tanh(x) = 1 - 2/(e^{2x}+1) via MUFU. |err| ~1e-7.
__device__ __forceinline__ float fast_tanh(float x) {
    float xc = fminf(fmaxf(x, -20.f), 20.f);
    float e;
    asm("ex2.approx.f32 %0, %1;" : "=f"(e) : "f"(xc * 2.8853900817779268f));
    float r;
    asm("rcp.approx.f32 %0, %1;" : "=f"(r) : "f"(e + 1.f));
    return fmaf(-2.f, r, 1.f);
}

// ---------------------------------------------------------------------------
// Kernel 1: pre1[t][b][j] = dot(emb[x[b,t]], Wih1[j]) + b_ih1[j] + b_hh1[j]
// (proven R1 version, unchanged)
// ---------------------------------------------------------------------------
__global__ __launch_bounds__(128) void k_pre1(
    const int* __restrict__ x, const float* __restrict__ emb,
    const float* __restrict__ Wih1, const float* __restrict__ bih1,
    const float* __restrict__ bhh1)
{
    __shared__ __align__(16) float shW[HID * 68];
    __shared__ __align__(16) float4 shE[8 * 16];
    __shared__ int shX[8];

    const int tid = threadIdx.x;

    for (int it = 0; it < 64; ++it) {
        int f = it * 128 + tid;
        int j = f >> 6, k = f & 63;
        shW[j * 68 + k] = Wih1[f];
    }
    __syncthreads();

    float Wr[64];
#pragma unroll
    for (int i = 0; i < 64; ++i) Wr[i] = shW[tid * 68 + i];
    const float bb = bih1[tid] + bhh1[tid];

    const int base = blockIdx.x * 256;
    const float4* __restrict__ e4 = (const float4*)emb;

    for (int it = 0; it < 32; ++it) {
        const int rid0 = base + it * 8;             // rid = t*256 + b
        if (tid < 8) {
            int rid = rid0 + tid;
            int t = rid >> 8, b = rid & 255;
            shX[tid] = x[b * TT + t];
        }
        __syncthreads();
        {
            int r = tid >> 4, f = tid & 15;
            shE[r * 16 + f] = e4[(long)shX[r] * 16 + f];
        }
        __syncthreads();

        float acc[8];
#pragma unroll
        for (int r = 0; r < 8; ++r) acc[r] = bb;
#pragma unroll
        for (int k4 = 0; k4 < 16; ++k4) {
#pragma unroll
            for (int r = 0; r < 8; ++r) {
                float4 e = shE[r * 16 + k4];
                acc[r] = fmaf(Wr[4 * k4 + 0], e.x, acc[r]);
                acc[r] = fmaf(Wr[4 * k4 + 1], e.y, acc[r]);
                acc[r] = fmaf(Wr[4 * k4 + 2], e.z, acc[r]);
                acc[r] = fmaf(Wr[4 * k4 + 3], e.w, acc[r]);
            }
        }
#pragma unroll
        for (int r = 0; r < 8; ++r)
            g_pre1[(long)(rid0 + r) * HID + tid] = acc[r];
        __syncthreads();
    }
}

// ---------------------------------------------------------------------------
// Layer scan core: 256 CTAs x 128 threads, ONE batch row per CTA, 2 CTAs/SM.
// Thread j holds the FULL recurrent row j as 64 packed f32x2 regs.
// Per step: 64 FFMA2 into 4 independent accs + 1 hsum + fast_tanh.
// Double-buffered h in smem, 1 barrier (4 warps) per step.
// ---------------------------------------------------------------------------
template<bool WRITE_OUT>
__device__ __forceinline__ void scan_core(
    const float* __restrict__ Whh, const float* __restrict__ preG,
    float* __restrict__ outG, float* __restrict__ h_final)
{
    __shared__ __align__(16) float hs[2][HID];

    const int j = threadIdx.x;
    const int b = blockIdx.x;

    u64t W2[64];
    {
        const ulonglong2* w = (const ulonglong2*)(Whh + j * HID);
#pragma unroll
        for (int i = 0; i < 32; ++i) {
            ulonglong2 a = w[i];
            W2[2 * i] = a.x; W2[2 * i + 1] = a.y;
        }
    }

    hs[0][j] = 0.f;
    hs[1][j] = 0.f;
    __syncthreads();

    const float* preBase = preG + (long)b * HID + j;
    float* outBase = WRITE_OUT ? (outG + (long)b * HID + j) : outG;

    // 2-deep prefetch pipeline for the pre[] stream.
    float pre_cur = preBase[0];
    float pre_nxt = preBase[(long)BB * HID];
    float hn = 0.f;

    for (int t = 0; t < TT; ++t) {
        const int cur = t & 1, nxt = cur ^ 1;
        float pre_use = pre_cur;
        pre_cur = pre_nxt;
        if (t + 2 < TT) pre_nxt = preBase[(long)(t + 2) * BB * HID];

        const ulonglong2* h2p = (const ulonglong2*)&hs[cur][0];
        u64t A0 = 0ull, A1 = 0ull, A2 = 0ull, A3 = 0ull;
#pragma unroll
        for (int i = 0; i < 16; ++i) {
            ulonglong2 u = h2p[2 * i];
            ffma2(A0, W2[4 * i + 0], u.x);
            ffma2(A1, W2[4 * i + 1], u.y);
            ulonglong2 v = h2p[2 * i + 1];
            ffma2(A2, W2[4 * i + 2], v.x);
            ffma2(A3, W2[4 * i + 3], v.y);
        }
        float dot = (hsum2(A0) + hsum2(A1)) + (hsum2(A2) + hsum2(A3));
        hn = fast_tanh(pre_use + dot);
        hs[nxt][j] = hn;
        if (WRITE_OUT) outBase[(long)t * BB * HID] = hn;
        __syncthreads();
    }

    if (h_final) h_final[b * HID + j] = hn;
}

__global__ __launch_bounds__(128, 2) void k_scan1(const float* __restrict__ Whh1)
{
    scan_core<true>(Whh1, g_pre1, g_out1, nullptr);
}

__global__ __launch_bounds__(128, 2) void k_scan2(const float* __restrict__ Whh2)
{
    scan_core<false>(Whh2, g_pre2, nullptr, g_h2);
}

// ---------------------------------------------------------------------------
// Kernel 3: pre2[rid][j] = dot(out1[rid], Wih2[j]) + b_ih2[j] + b_hh2[j]
// 512 blocks x 256 threads; two 128-thread groups, 8-row staging, f32x2 FMAs.
// ---------------------------------------------------------------------------
__global__ __launch_bounds__(256) void k_pre2(
    const float* __restrict__ Wih2, const float* __restrict__ bih2,
    const float* __restrict__ bhh2)
{
    __shared__ __align__(16) float shW[HID * 129];
    __shared__ __align__(16) float4 shE[2][8][33];   // [group][row][float4 col]

    const int tid = threadIdx.x;
    const int g = tid >> 7;          // group 0/1
    const int j = tid & 127;         // feature

    for (int it = 0; it < 64; ++it) {
        int f = it * 256 + tid;
        int row = f >> 7, col = f & 127;
        shW[row * 129 + col] = Wih2[f];
    }
    __syncthreads();

    u64t W2[64];
    {
        const float* wrow = &shW[j * 129];
#pragma unroll
        for (int i = 0; i < 64; ++i)
            W2[i] = pack2(wrow[2 * i], wrow[2 * i + 1]);
    }
    const float bb = bih2[j] + bhh2[j];

    const long base = (long)blockIdx.x * 256 + g * 128;
    const float4* __restrict__ o4 = (const float4*)g_out1;

    for (int it = 0; it < 16; ++it) {
        const long rid0 = base + it * 8;
        {
            int rr = j >> 4, c = j & 15;
            shE[g][rr][c] = o4[(rid0 + rr) * 32 + c];
            shE[g][rr][c + 16] = o4[(rid0 + rr) * 32 + c + 16];
        }
        __syncthreads();

        u64t acc2[8];
#pragma unroll
        for (int r = 0; r < 8; ++r) acc2[r] = 0ull;
#pragma unroll
        for (int k4 = 0; k4 < 32; ++k4) {
#pragma unroll
            for (int r = 0; r < 8; ++r) {
                ulonglong2 e = *(const ulonglong2*)&shE[g][r][k4];
                ffma2(acc2[r], W2[2 * k4 + 0], e.x);
                ffma2(acc2[r], W2[2 * k4 + 1], e.y);
            }
        }
#pragma unroll
        for (int r = 0; r < 8; ++r)
            g_pre2[(rid0 + r) * HID + j] = hsum2(acc2[r]) + bb;
        __syncthreads();
    }
}

// ---------------------------------------------------------------------------
// Kernel 5: epilogue — LN -> proj -> tanh -> LN. One block per batch row.
// ---------------------------------------------------------------------------
__global__ __launch_bounds__(128) void k_epi(
    const float* __restrict__ ln_g, const float* __restrict__ ln_b,
    const float* __restrict__ projW, const float* __restrict__ proj_b,
    const float* __restrict__ on_g, const float* __restrict__ on_b,
    float* __restrict__ out)
{
    __shared__ __align__(16) float sh_rep[HID];
    __shared__ float sh_red[8];

    const int j = threadIdx.x;
    const int b = blockIdx.x;

    float v = g_h2[b * HID + j];

    float s = v, q = v * v;
#pragma unroll
    for (int o = 16; o; o >>= 1) {
        s += __shfl_xor_sync(0xffffffffu, s, o);
        q += __shfl_xor_sync(0xffffffffu, q, o);
    }
    if ((j & 31) == 0) { sh_red[j >> 5] = s; sh_red[4 + (j >> 5)] = q; }
    __syncthreads();
    s = sh_red[0] + sh_red[1] + sh_red[2] + sh_red[3];
    q = sh_red[4] + sh_red[5] + sh_red[6] + sh_red[7];
    float mu = s * (1.f / HID);
    float var = q * (1.f / HID) - mu * mu;
    float rep = (v - mu) * rsqrtf(var + 1e-5f) * ln_g[j] + ln_b[j];
    sh_rep[j] = rep;
    __syncthreads();

    float acc = proj_b[j];
    const float4* w4 = (const float4*)(projW + j * HID);
    const float4* r4 = (const float4*)sh_rep;
#pragma unroll
    for (int i = 0; i < 32; ++i) {
        float4 w = __ldg(&w4[i]);
        float4 r = r4[i];
        acc = fmaf(w.x, r.x, acc);
        acc = fmaf(w.y, r.y, acc);
        acc = fmaf(w.z, r.z, acc);
        acc = fmaf(w.w, r.w, acc);
    }
    float tv = tanhf(acc);

    __syncthreads();
    s = tv; q = tv * tv;
#pragma unroll
    for (int o = 16; o; o >>= 1) {
        s += __shfl_xor_sync(0xffffffffu, s, o);
        q += __shfl_xor_sync(0xffffffffu, q, o);
    }
    if ((j & 31) == 0) { sh_red[j >> 5] = s; sh_red[4 + (j >> 5)] = q; }
    __syncthreads();
    s = sh_red[0] + sh_red[1] + sh_red[2] + sh_red[3];
    q = sh_red[4] + sh_red[5] + sh_red[6] + sh_red[7];
    float mu2 = s * (1.f / HID);
    float var2 = q * (1.f / HID) - mu2 * mu2;
    out[b * HID + j] = (tv - mu2) * rsqrtf(var2 + 1e-5f) * on_g[j] + on_b[j];
}

// ---------------------------------------------------------------------------
extern "C" void kernel_launch(void* const* d_in, const int* in_sizes, int n_in,
                              void* d_out, int out_size)
{
    const int*   x     = (const int*)  d_in[0];
    const float* emb   = (const float*)d_in[1];
    const float* Wih1  = (const float*)d_in[2];
    const float* bih1  = (const float*)d_in[3];
    const float* Whh1  = (const float*)d_in[4];
    const float* bhh1  = (const float*)d_in[5];
    const float* Wih2  = (const float*)d_in[6];
    const float* bih2  = (const float*)d_in[7];
    const float* Whh2  = (const float*)d_in[8];
    const float* bhh2  = (const float*)d_in[9];
    const float* ln_g  = (const float*)d_in[10];
    const float* ln_b  = (const float*)d_in[11];
    const float* projW = (const float*)d_in[12];
    const float* projb = (const float*)d_in[13];
    const float* on_g  = (const float*)d_in[14];
    const float* on_b  = (const float*)d_in[15];

    k_pre1<<<512, 128>>>(x, emb, Wih1, bih1, bhh1);
    k_scan1<<<256, 128>>>(Whh1);
    k_pre2<<<512, 256>>>(Wih2, bih2, bhh2);
    k_scan2<<<256, 128>>>(Whh2);
    k_epi<<<256, 128>>>(ln_g, ln_b, projW, projb, on_g, on_b, (float*)d_out);
}

// round 9
// speedup vs baseline: 1.6740x; 1.6740x over previous
#include <cuda_runtime.h>

#define BB 256
#define TT 512
#define EMBD 64
#define HID 128

__device__ float g_pre1[(long)TT * BB * HID];   // [t][b][j], 64 MB
__device__ float g_h2[BB * HID];

// tanh(x) = 1 - 2/(e^{2x}+1) via MUFU. |err| ~1e-7 per call.
__device__ __forceinline__ float fast_tanh(float x) {
    float xc = fminf(fmaxf(x, -20.f), 20.f);
    float e;
    asm("ex2.approx.f32 %0, %1;" : "=f"(e) : "f"(xc * 2.8853900817779268f));
    float r;
    asm("rcp.approx.f32 %0, %1;" : "=f"(r) : "f"(e + 1.f));
    return fmaf(-2.f, r, 1.f);
}

// ---------------------------------------------------------------------------
// Kernel 1: pre1[t][b][j] = dot(emb[x[b,t]], Wih1[j]) + b_ih1[j] + b_hh1[j]
// (proven R1 version, byte-identical)
// ---------------------------------------------------------------------------
__global__ __launch_bounds__(128) void k_pre1(
    const int* __restrict__ x, const float* __restrict__ emb,
    const float* __restrict__ Wih1, const float* __restrict__ bih1,
    const float* __restrict__ bhh1)
{
    __shared__ __align__(16) float shW[HID * 68];
    __shared__ __align__(16) float4 shE[8 * 16];
    __shared__ int shX[8];

    const int tid = threadIdx.x;

    for (int it = 0; it < 64; ++it) {
        int f = it * 128 + tid;
        int j = f >> 6, k = f & 63;
        shW[j * 68 + k] = Wih1[f];
    }
    __syncthreads();

    float Wr[64];
#pragma unroll
    for (int i = 0; i < 64; ++i) Wr[i] = shW[tid * 68 + i];
    const float bb = bih1[tid] + bhh1[tid];

    const int base = blockIdx.x * 256;
    const float4* __restrict__ e4 = (const float4*)emb;

    for (int it = 0; it < 32; ++it) {
        const int rid0 = base + it * 8;             // rid = t*256 + b
        if (tid < 8) {
            int rid = rid0 + tid;
            int t = rid >> 8, b = rid & 255;
            shX[tid] = x[b * TT + t];
        }
        __syncthreads();
        {
            int r = tid >> 4, f = tid & 15;
            shE[r * 16 + f] = e4[(long)shX[r] * 16 + f];
        }
        __syncthreads();

        float acc[8];
#pragma unroll
        for (int r = 0; r < 8; ++r) acc[r] = bb;
#pragma unroll
        for (int k4 = 0; k4 < 16; ++k4) {
#pragma unroll
            for (int r = 0; r < 8; ++r) {
                float4 e = shE[r * 16 + k4];
                acc[r] = fmaf(Wr[4 * k4 + 0], e.x, acc[r]);
                acc[r] = fmaf(Wr[4 * k4 + 1], e.y, acc[r]);
                acc[r] = fmaf(Wr[4 * k4 + 2], e.z, acc[r]);
                acc[r] = fmaf(Wr[4 * k4 + 3], e.w, acc[r]);
            }
        }
#pragma unroll
        for (int r = 0; r < 8; ++r)
            g_pre1[(long)(rid0 + r) * HID + tid] = acc[r];
        __syncthreads();
    }
}

// ---------------------------------------------------------------------------
// Kernel 2: fused two-layer scan — R1 structure exactly, plus:
//   * split accumulators (2 per dot) to halve FMA chain depth
//   * fast_tanh in the combine phases
// 128 blocks x 256 threads; block handles rows b0,b0+1.
// Thread (j = tid&127, p = tid>>7) holds k-half rows of W_hh1/W_ih2/W_hh2.
// ---------------------------------------------------------------------------
__global__ __launch_bounds__(256, 1) void k_scan(
    const float* __restrict__ Whh1, const float* __restrict__ Wih2,
    const float* __restrict__ Whh2, const float* __restrict__ bih2,
    const float* __restrict__ bhh2)
{
    __shared__ __align__(16) float sh_h1[2][HID];
    __shared__ __align__(16) float sh_h2[2][HID];
    __shared__ __align__(16) float sh_p[2][2][HID];   // [half][row][j]

    const int tid = threadIdx.x;
    const int j = tid & 127;
    const int p = tid >> 7;            // k-half (uniform per warp)
    const int b0 = blockIdx.x * 2;

    float W1r[64], Wi2r[64], W2r[64];
    {
        const float* w1 = Whh1 + j * HID + p * 64;
        const float* wi = Wih2 + j * HID + p * 64;
        const float* w2 = Whh2 + j * HID + p * 64;
#pragma unroll
        for (int i = 0; i < 64; ++i) { W1r[i] = w1[i]; Wi2r[i] = wi[i]; W2r[i] = w2[i]; }
    }
    const float bb2 = bih2[j] + bhh2[j];

    sh_h1[p][j] = 0.f;
    sh_h2[p][j] = 0.f;
    __syncthreads();

    const float* preBase = g_pre1 + (long)(b0 + p) * HID + j;
    float pre_r = preBase[0];

    const float4* h0p = (const float4*)&sh_h1[0][p * 64];
    const float4* h1p = (const float4*)&sh_h1[1][p * 64];
    const float4* g0p = (const float4*)&sh_h2[0][p * 64];
    const float4* g1p = (const float4*)&sh_h2[1][p * 64];

    for (int t = 0; t < TT; ++t) {
        // ---- Phase A: partials of W_hh1 * h1 for both rows (split accs) ----
        float a0x = 0.f, a0y = 0.f, a1x = 0.f, a1y = 0.f;
#pragma unroll
        for (int i = 0; i < 16; ++i) {
            float4 h0 = h0p[i];
            a0x = fmaf(W1r[4 * i + 0], h0.x, a0x);
            a0y = fmaf(W1r[4 * i + 1], h0.y, a0y);
            a0x = fmaf(W1r[4 * i + 2], h0.z, a0x);
            a0y = fmaf(W1r[4 * i + 3], h0.w, a0y);
            float4 h1 = h1p[i];
            a1x = fmaf(W1r[4 * i + 0], h1.x, a1x);
            a1y = fmaf(W1r[4 * i + 1], h1.y, a1y);
            a1x = fmaf(W1r[4 * i + 2], h1.z, a1x);
            a1y = fmaf(W1r[4 * i + 3], h1.w, a1y);
        }
        sh_p[p][0][j] = a0x + a0y;
        sh_p[p][1][j] = a1x + a1y;
        __syncthreads();

        // ---- Phase B: combine + tanh; thread (j,p) combines row p ----
        {
            float v = pre_r + sh_p[0][p][j] + sh_p[1][p][j];
            sh_h1[p][j] = fast_tanh(v);
        }
        if (t + 1 < TT) pre_r = preBase[(long)(t + 1) * BB * HID];
        __syncthreads();

        // ---- Phase C: partials of W_ih2*h1new + W_hh2*h2 (split accs) ----
        float c0x = 0.f, c0y = 0.f, c1x = 0.f, c1y = 0.f;
        float d0x = 0.f, d0y = 0.f, d1x = 0.f, d1y = 0.f;
#pragma unroll
        for (int i = 0; i < 16; ++i) {
            float4 h0 = h0p[i];
            c0x = fmaf(Wi2r[4 * i + 0], h0.x, c0x);
            c0y = fmaf(Wi2r[4 * i + 1], h0.y, c0y);
            c0x = fmaf(Wi2r[4 * i + 2], h0.z, c0x);
            c0y = fmaf(Wi2r[4 * i + 3], h0.w, c0y);
            float4 h1 = h1p[i];
            c1x = fmaf(Wi2r[4 * i + 0], h1.x, c1x);
            c1y = fmaf(Wi2r[4 * i + 1], h1.y, c1y);
            c1x = fmaf(Wi2r[4 * i + 2], h1.z, c1x);
            c1y = fmaf(Wi2r[4 * i + 3], h1.w, c1y);
            float4 g0 = g0p[i];
            d0x = fmaf(W2r[4 * i + 0], g0.x, d0x);
            d0y = fmaf(W2r[4 * i + 1], g0.y, d0y);
            d0x = fmaf(W2r[4 * i + 2], g0.z, d0x);
            d0y = fmaf(W2r[4 * i + 3], g0.w, d0y);
            float4 g1 = g1p[i];
            d1x = fmaf(W2r[4 * i + 0], g1.x, d1x);
            d1y = fmaf(W2r[4 * i + 1], g1.y, d1y);
            d1x = fmaf(W2r[4 * i + 2], g1.z, d1x);
            d1y = fmaf(W2r[4 * i + 3], g1.w, d1y);
        }
        sh_p[p][0][j] = (c0x + c0y) + (d0x + d0y);
        sh_p[p][1][j] = (c1x + c1y) + (d1x + d1y);
        __syncthreads();

        // ---- Phase D: combine + tanh for h2 ----
        {
            float v2 = bb2 + sh_p[0][p][j] + sh_p[1][p][j];
            sh_h2[p][j] = fast_tanh(v2);
        }
        __syncthreads();
    }

    g_h2[(b0 + p) * HID + j] = sh_h2[p][j];
}

// ---------------------------------------------------------------------------
// Kernel 3: epilogue — LN -> proj -> tanh -> LN. One block per batch row.
// ---------------------------------------------------------------------------
__global__ __launch_bounds__(128) void k_epi(
    const float* __restrict__ ln_g, const float* __restrict__ ln_b,
    const float* __restrict__ projW, const float* __restrict__ proj_b,
    const float* __restrict__ on_g, const float* __restrict__ on_b,
    float* __restrict__ out)
{
    __shared__ __align__(16) float sh_rep[HID];
    __shared__ float sh_red[8];

    const int j = threadIdx.x;
    const int b = blockIdx.x;

    float v = g_h2[b * HID + j];

    // LN 1
    float s = v, q = v * v;
#pragma unroll
    for (int o = 16; o; o >>= 1) {
        s += __shfl_xor_sync(0xffffffffu, s, o);
        q += __shfl_xor_sync(0xffffffffu, q, o);
    }
    if ((j & 31) == 0) { sh_red[j >> 5] = s; sh_red[4 + (j >> 5)] = q; }
    __syncthreads();
    s = sh_red[0] + sh_red[1] + sh_red[2] + sh_red[3];
    q = sh_red[4] + sh_red[5] + sh_red[6] + sh_red[7];
    float mu = s * (1.f / HID);
    float var = q * (1.f / HID) - mu * mu;
    float rep = (v - mu) * rsqrtf(var + 1e-5f) * ln_g[j] + ln_b[j];
    sh_rep[j] = rep;
    __syncthreads();

    // proj + tanh
    float acc = proj_b[j];
    const float4* w4 = (const float4*)(projW + j * HID);
    const float4* r4 = (const float4*)sh_rep;
#pragma unroll
    for (int i = 0; i < 32; ++i) {
        float4 w = __ldg(&w4[i]);
        float4 r = r4[i];
        acc = fmaf(w.x, r.x, acc);
        acc = fmaf(w.y, r.y, acc);
        acc = fmaf(w.z, r.z, acc);
        acc = fmaf(w.w, r.w, acc);
    }
    float tv = tanhf(acc);

    // LN 2
    __syncthreads();
    s = tv; q = tv * tv;
#pragma unroll
    for (int o = 16; o; o >>= 1) {
        s += __shfl_xor_sync(0xffffffffu, s, o);
        q += __shfl_xor_sync(0xffffffffu, q, o);
    }
    if ((j & 31) == 0) { sh_red[j >> 5] = s; sh_red[4 + (j >> 5)] = q; }
    __syncthreads();
    s = sh_red[0] + sh_red[1] + sh_red[2] + sh_red[3];
    q = sh_red[4] + sh_red[5] + sh_red[6] + sh_red[7];
    float mu2 = s * (1.f / HID);
    float var2 = q * (1.f / HID) - mu2 * mu2;
    out[b * HID + j] = (tv - mu2) * rsqrtf(var2 + 1e-5f) * on_g[j] + on_b[j];
}

// ---------------------------------------------------------------------------
extern "C" void kernel_launch(void* const* d_in, const int* in_sizes, int n_in,
                              void* d_out, int out_size)
{
    const int*   x     = (const int*)  d_in[0];
    const float* emb   = (const float*)d_in[1];
    const float* Wih1  = (const float*)d_in[2];
    const float* bih1  = (const float*)d_in[3];
    const float* Whh1  = (const float*)d_in[4];
    const float* bhh1  = (const float*)d_in[5];
    const float* Wih2  = (const float*)d_in[6];
    const float* bih2  = (const float*)d_in[7];
    const float* Whh2  = (const float*)d_in[8];
    const float* bhh2  = (const float*)d_in[9];
    const float* ln_g  = (const float*)d_in[10];
    const float* ln_b  = (const float*)d_in[11];
    const float* projW = (const float*)d_in[12];
    const float* projb = (const float*)d_in[13];
    const float* on_g  = (const float*)d_in[14];
    const float* on_b  = (const float*)d_in[15];

    k_pre1<<<512, 128>>>(x, emb, Wih1, bih1, bhh1);
    k_scan<<<128, 256>>>(Whh1, Wih2, Whh2, bih2, bhh2);
    k_epi<<<256, 128>>>(ln_g, ln_b, projW, projb, on_g, on_b, (float*)d_out);
}